// round 7
// baseline (speedup 1.0000x reference)
#include <cuda_runtime.h>
#include <cuda_bf16.h>

#define D 8192
#define BATCH 4096
#define ROWS_PER_BLOCK 16
#define GRID_X (D / 1024)                        // 8
#define GRID_Y (BATCH / ROWS_PER_BLOCK)          // 256
#define NBLK   (GRID_X * GRID_Y)                 // 2048
#define NPROD  16                                // producer blocks (by 0..1)

__device__ float d_z[D];      // after high-bit FWHT stages
__device__ int   d_flag;      // producer completions (0..16)
__device__ int   d_done;      // finished blocks (generation-safe reset)

__device__ __forceinline__ int ld_vol(const int* p) {
    int v;
    asm volatile("ld.volatile.global.s32 %0, [%1];" : "=r"(v) : "l"(p));
    return v;
}

// ---------------------------------------------------------------------------
// Single fused kernel.  j = g*128 + low (g: 6 bits, low: 7 bits).
//   Producers (16 lowest-bid blocks, one warp per low): softplus + s1[0] +
//   high-bit FWHT stages (g bits) via pure shfl.xor — no smem, no syncthreads,
//   one flag.  (This is R3's stageA, which gave the best results.)
//   All 2048 blocks: preload x/s2, spin on the flag, finish the low-bit
//   stages warp-locally (R3's validated outer body), stream the outer product.
// ---------------------------------------------------------------------------
__global__ __launch_bounds__(256)
void whvi_fused_kernel(const float* __restrict__ x,
                       const float* __restrict__ s1,
                       const float* __restrict__ s2,
                       const float* __restrict__ g_mu,
                       const float* __restrict__ g_rho,
                       const float* __restrict__ eps,
                       float* __restrict__ out) {
    __shared__ float sw[1024];
    const int t    = threadIdx.x;
    const int lane = t & 31;
    const int wi   = t >> 5;
    const int bx   = blockIdx.x;
    const int by   = blockIdx.y;

    // ===================== producer role (by < 2) ==========================
    if (by < 2) {
        const int low = (by * 8 + bx) * 8 + wi;      // 0..127
        const float s10 = __ldg(s1);
        const int e0 = lane * 128 + low;             // g = lane
        const int e1 = e0 + 32 * 128;                // g = lane + 32

        float v0 = __ldg(g_rho + e0), v1 = __ldg(g_rho + e1);
        float m0 = __ldg(g_mu  + e0), m1 = __ldg(g_mu  + e1);
        float p0 = __ldg(eps   + e0), p1 = __ldg(eps   + e1);
        float sp0 = fmaxf(v0, 0.0f) + __logf(1.0f + __expf(-fabsf(v0)));
        float sp1 = fmaxf(v1, 0.0f) + __logf(1.0f + __expf(-fabsf(v1)));
        float r0 = s10 * fmaf(sp0, p0, m0);
        float r1 = s10 * fmaf(sp1, p1, m1);

        // g bits 0..4 via shfl.xor (element strides 128..2048)
        #pragma unroll
        for (int mm = 1; mm <= 16; mm <<= 1) {
            const float sgn = (lane & mm) ? -1.0f : 1.0f;
            float o0 = __shfl_xor_sync(0xffffffffu, r0, mm);
            float o1 = __shfl_xor_sync(0xffffffffu, r1, mm);
            r0 = fmaf(sgn, r0, o0);
            r1 = fmaf(sgn, r1, o1);
        }
        // g bit 5 (stride 4096)
        d_z[e0] = r0 + r1;
        d_z[e1] = r0 - r1;

        __threadfence();
        __syncthreads();
        if (t == 0) atomicAdd(&d_flag, 1);
    }

    // ===================== consumer prologue (all blocks) ==================
    const int b0 = by * ROWS_PER_BLOCK;
    float xs[ROWS_PER_BLOCK];
    #pragma unroll
    for (int q = 0; q < ROWS_PER_BLOCK; q++)
        xs[q] = __ldg(x + b0 + q);

    const int jb   = bx * 1024;
    const int base = jb + wi * 128 + lane;           // warp wi owns 128-group wi
    float s2v[4];
    #pragma unroll
    for (int k = 0; k < 4; k++)
        s2v[k] = __ldg(s2 + base + k * 32);

    // ===================== wait for all 16 producers =======================
    if (t == 0) {
        while (ld_vol(&d_flag) < NPROD) { __nanosleep(32); }
    }
    __syncthreads();
    __threadfence();

    // ===================== low-bit stages (strides 1..64) ==================
    float rr[4];
    #pragma unroll
    for (int k = 0; k < 4; k++)
        rr[k] = d_z[base + k * 32];

    #pragma unroll
    for (int mm = 1; mm <= 16; mm <<= 1) {           // lane bits: strides 1..16
        const float sgn = (lane & mm) ? -1.0f : 1.0f;
        #pragma unroll
        for (int k = 0; k < 4; k++) {
            float o = __shfl_xor_sync(0xffffffffu, rr[k], mm);
            rr[k] = fmaf(sgn, rr[k], o);
        }
    }
    { // stride 32 (k bit 0)
        float a0 = rr[0], c0 = rr[1], a1 = rr[2], c1 = rr[3];
        rr[0] = a0 + c0; rr[1] = a0 - c0;
        rr[2] = a1 + c1; rr[3] = a1 - c1;
    }
    { // stride 64 (k bit 1)
        float a0 = rr[0], c0 = rr[2], a1 = rr[1], c1 = rr[3];
        rr[0] = a0 + c0; rr[2] = a0 - c0;
        rr[1] = a1 + c1; rr[3] = a1 - c1;
    }

    // apply s2, transpose through smem so each thread owns 4 contiguous cols
    #pragma unroll
    for (int k = 0; k < 4; k++)
        sw[wi * 128 + k * 32 + lane] = s2v[k] * rr[k];
    __syncthreads();

    const float4 w4 = *(const float4*)&sw[t * 4];
    const int jbase = jb + t * 4;

    // ===================== stream the outer product ========================
    #pragma unroll
    for (int q = 0; q < ROWS_PER_BLOCK; q++) {
        float xv = xs[q];
        float4 o = make_float4(xv * w4.x, xv * w4.y, xv * w4.z, xv * w4.w);
        // 134 MB output, never re-read -> streaming (evict-first) store
        __stcs((float4*)(out + (size_t)(b0 + q) * D + jbase), o);
    }

    // ===================== generation-safe counter reset ===================
    __syncthreads();
    if (t == 0) {
        int dn = atomicAdd(&d_done, 1);
        if (dn == NBLK - 1) {
            atomicExch(&d_flag, 0);
            atomicExch(&d_done, 0);
        }
    }
}

extern "C" void kernel_launch(void* const* d_in, const int* in_sizes, int n_in,
                              void* d_out, int out_size) {
    const float* x     = (const float*)d_in[0];  // (4096, 1)
    const float* s1    = (const float*)d_in[1];  // (8192,)
    const float* s2    = (const float*)d_in[2];  // (8192,)
    const float* g_mu  = (const float*)d_in[3];  // (8192,)
    const float* g_rho = (const float*)d_in[4];  // (8192,)
    const float* eps   = (const float*)d_in[5];  // (8192,)
    float* out = (float*)d_out;                  // (4096, 8192) f32

    dim3 grid(GRID_X, GRID_Y);                   // (8, 256)
    whvi_fused_kernel<<<grid, 256>>>(x, s1, s2, g_mu, g_rho, eps, out);
}

// round 8
// speedup vs baseline: 1.0234x; 1.0234x over previous
#include <cuda_runtime.h>
#include <cuda_bf16.h>
#include <cstdint>

#define D 8192
#define BATCH 4096
#define ROWS_PER_BLOCK 16

// Intermediate z = s1[0] * (H_64 (x) I_128) g_tilde  (high-bit FWHT stages done).
__device__ float d_z[D];

// ---------------------------------------------------------------------------
// Kernel 1 (R3's stageA, best measured): high-bit stages (element strides
// 128..4096) via pure shfl.xor, one warp per low index. 16 blocks x 256 thr.
// Folds in g_tilde = g_mu + softplus(g_rho)*eps and the s1[0] scale.
// ---------------------------------------------------------------------------
__global__ __launch_bounds__(256, 1)
void stageA_kernel(const float* __restrict__ s1,
                   const float* __restrict__ g_mu,
                   const float* __restrict__ g_rho,
                   const float* __restrict__ eps) {
#if __CUDA_ARCH__ >= 900
    cudaTriggerProgrammaticLaunchCompletion();
#endif
    const int lane = threadIdx.x & 31;
    const int wi   = threadIdx.x >> 5;
    const int low  = blockIdx.x * 8 + wi;        // 0..127
    const float s10 = __ldg(s1);

    const int e0 = lane * 128 + low;             // g = lane
    const int e1 = e0 + 32 * 128;                // g = lane + 32

    float r0, r1;
    {
        float v0 = __ldg(g_rho + e0), v1 = __ldg(g_rho + e1);
        float sp0 = fmaxf(v0, 0.0f) + __logf(1.0f + __expf(-fabsf(v0)));
        float sp1 = fmaxf(v1, 0.0f) + __logf(1.0f + __expf(-fabsf(v1)));
        r0 = s10 * fmaf(sp0, __ldg(eps + e0), __ldg(g_mu + e0));
        r1 = s10 * fmaf(sp1, __ldg(eps + e1), __ldg(g_mu + e1));
    }

    #pragma unroll
    for (int m = 1; m <= 16; m <<= 1) {          // g bits 0..4
        const float sgn = (lane & m) ? -1.0f : 1.0f;
        float o0 = __shfl_xor_sync(0xffffffffu, r0, m);
        float o1 = __shfl_xor_sync(0xffffffffu, r1, m);
        r0 = fmaf(sgn, r0, o0);
        r1 = fmaf(sgn, r1, o1);
    }
    d_z[e0] = r0 + r1;                           // g bit 5
    d_z[e1] = r0 - r1;
}

// ---------------------------------------------------------------------------
// Kernel 2: low-bit FWHT stages + s2 (R3's validated body), then the rank-1
// outer product written via TMA BULK STORES: stage 4 rows (16KB) in smem,
// cp.async.bulk smem->gmem, double-buffered. Bypasses L1tex / per-thread STG
// issue, which R7's counters (L1 62%, nothing else saturated) implicate as
// the store bottleneck.
// ---------------------------------------------------------------------------
__global__ __launch_bounds__(256)
void outer_kernel(const float* __restrict__ x,
                  const float* __restrict__ s2,
                  float* __restrict__ out) {
    __shared__ float sw[1024];
    __shared__ __align__(16) float buf[2][4][1024];   // 2 x 16KB staging
    const int tid  = threadIdx.x;
    const int lane = tid & 31;
    const int r    = tid >> 5;
    const int jb   = blockIdx.x * 1024;
    const int base = jb + r * 128 + lane;
    const int b0   = blockIdx.y * ROWS_PER_BLOCK;

    // ---- prologue independent of kernel 1 ----
    float xs[ROWS_PER_BLOCK];
    #pragma unroll
    for (int q = 0; q < ROWS_PER_BLOCK; q++)
        xs[q] = __ldg(x + b0 + q);

    float s2v[4];
    #pragma unroll
    for (int k = 0; k < 4; k++)
        s2v[k] = __ldg(s2 + base + k * 32);

#if __CUDA_ARCH__ >= 900
    cudaGridDependencySynchronize();              // wait for d_z
#endif

    // ---- low-bit stages (strides 1..64) ----
    float rr[4];
    #pragma unroll
    for (int k = 0; k < 4; k++)
        rr[k] = d_z[base + k * 32];

    #pragma unroll
    for (int m = 1; m <= 16; m <<= 1) {
        const float sgn = (lane & m) ? -1.0f : 1.0f;
        #pragma unroll
        for (int k = 0; k < 4; k++) {
            float o = __shfl_xor_sync(0xffffffffu, rr[k], m);
            rr[k] = fmaf(sgn, rr[k], o);
        }
    }
    { // stride 32
        float a0 = rr[0], c0 = rr[1], a1 = rr[2], c1 = rr[3];
        rr[0] = a0 + c0; rr[1] = a0 - c0;
        rr[2] = a1 + c1; rr[3] = a1 - c1;
    }
    { // stride 64
        float a0 = rr[0], c0 = rr[2], a1 = rr[1], c1 = rr[3];
        rr[0] = a0 + c0; rr[2] = a0 - c0;
        rr[1] = a1 + c1; rr[3] = a1 - c1;
    }

    #pragma unroll
    for (int k = 0; k < 4; k++)
        sw[r * 128 + k * 32 + lane] = s2v[k] * rr[k];
    __syncthreads();

    const float4 w4 = *(const float4*)&sw[tid * 4];

    // ---- 4 groups of 4 rows, double-buffered TMA bulk stores ----
    #pragma unroll
    for (int g = 0; g < 4; g++) {
        if (g >= 2) {
            if (tid == 0)
                asm volatile("cp.async.bulk.wait_group.read 1;" ::: "memory");
            __syncthreads();                       // buf[g&1] free for reuse
        }
        #pragma unroll
        for (int q = 0; q < 4; q++) {
            float xv = xs[g * 4 + q];
            float4 o = make_float4(xv * w4.x, xv * w4.y, xv * w4.z, xv * w4.w);
            *(float4*)&buf[g & 1][q][tid * 4] = o;
        }
        __syncthreads();
        if (tid == 0) {
            asm volatile("fence.proxy.async.shared::cta;" ::: "memory");
            #pragma unroll
            for (int q = 0; q < 4; q++) {
                const float* dst = out + (size_t)(b0 + g * 4 + q) * D + jb;
                uint32_t saddr;
                asm("{ .reg .u64 a; cvta.to.shared.u64 a, %1; cvt.u32.u64 %0, a; }"
                    : "=r"(saddr) : "l"(&buf[g & 1][q][0]));
                asm volatile(
                    "cp.async.bulk.global.shared::cta.bulk_group [%0], [%1], %2;"
                    :: "l"(dst), "r"(saddr), "n"(4096) : "memory");
            }
            asm volatile("cp.async.bulk.commit_group;" ::: "memory");
        }
    }
    // Full completion (writes committed) before block exit.
    if (tid == 0)
        asm volatile("cp.async.bulk.wait_group 0;" ::: "memory");
}

extern "C" void kernel_launch(void* const* d_in, const int* in_sizes, int n_in,
                              void* d_out, int out_size) {
    const float* x     = (const float*)d_in[0];  // (4096, 1)
    const float* s1    = (const float*)d_in[1];  // (8192,)
    const float* s2    = (const float*)d_in[2];  // (8192,)
    const float* g_mu  = (const float*)d_in[3];  // (8192,)
    const float* g_rho = (const float*)d_in[4];  // (8192,)
    const float* eps   = (const float*)d_in[5];  // (8192,)
    float* out = (float*)d_out;                  // (4096, 8192) f32

    stageA_kernel<<<16, 256>>>(s1, g_mu, g_rho, eps);

    cudaLaunchConfig_t cfg = {};
    cfg.gridDim  = dim3(D / 1024, BATCH / ROWS_PER_BLOCK, 1);  // (8, 256)
    cfg.blockDim = dim3(256, 1, 1);
    cfg.stream   = 0;
    cudaLaunchAttribute attr;
    attr.id = cudaLaunchAttributeProgrammaticStreamSerialization;
    attr.val.programmaticStreamSerializationAllowed = 1;
    cfg.attrs    = &attr;
    cfg.numAttrs = 1;
    cudaLaunchKernelEx(&cfg, outer_kernel, x, s2, out);
}

// round 9
// speedup vs baseline: 1.1709x; 1.1441x over previous
#include <cuda_runtime.h>
#include <cuda_bf16.h>

#define D 8192
#define BATCH 4096
#define ROWS_PER_BLOCK 16

// Intermediate: FWHT bits 10..12 applied (strides 1024/2048/4096), s1[0] folded.
__device__ float d_z[D];

// ---------------------------------------------------------------------------
// stageA: softplus + s1[0] + FWHT stages on bits 10..12 ONLY. Thread i owns
// elements {i + j*1024 : j=0..7}; warp loads are perfect 128B segments, MLP=24.
// 16 blocks x 64 threads. (Stages commute bit-wise, so this order is valid.)
// ---------------------------------------------------------------------------
__global__ __launch_bounds__(64, 1)
void stageA_kernel(const float* __restrict__ s1,
                   const float* __restrict__ g_mu,
                   const float* __restrict__ g_rho,
                   const float* __restrict__ eps) {
#if __CUDA_ARCH__ >= 900
    cudaTriggerProgrammaticLaunchCompletion();
#endif
    const int i = blockIdx.x * 64 + threadIdx.x;     // 0..1023
    const float s10 = __ldg(s1);

    float rh[8], mu[8], ep[8];
    #pragma unroll
    for (int j = 0; j < 8; j++) {                    // issue all loads first
        rh[j] = __ldg(g_rho + i + j * 1024);
        mu[j] = __ldg(g_mu  + i + j * 1024);
        ep[j] = __ldg(eps   + i + j * 1024);
    }
    float r[8];
    #pragma unroll
    for (int j = 0; j < 8; j++) {
        float sp = fmaxf(rh[j], 0.0f) + __logf(1.0f + __expf(-fabsf(rh[j])));
        r[j] = s10 * fmaf(sp, ep[j], mu[j]);
    }
    // 8-point FWHT over j (bits 10..12 of the element index)
    #pragma unroll
    for (int s = 1; s < 8; s <<= 1) {
        #pragma unroll
        for (int j = 0; j < 8; j++) {
            if (!(j & s)) {
                float a = r[j], b = r[j | s];
                r[j]     = a + b;
                r[j | s] = a - b;
            }
        }
    }
    #pragma unroll
    for (int j = 0; j < 8; j++)
        d_z[i + j * 1024] = r[j];                    // coalesced stores
}

// ---------------------------------------------------------------------------
// outer: full 1024-pt FWHT (bits 0..9) of its contiguous chunk, apply s2,
// then the rank-1 outer product (R3's store body, measured at roofline).
// Mapping A: n = wi*128 + k*32 + lane  (lane=bits0..4, k=bits5..6, wi=bits7..9)
// Mapping B: n = lane*32 + wi*4 + m   (lane bits2..4 = n bits7..9 -> shfl)
// Padded smem (+1 float per 32) keeps both transposes conflict-free.
// ---------------------------------------------------------------------------
__global__ __launch_bounds__(256)
void outer_kernel(const float* __restrict__ x,
                  const float* __restrict__ s2,
                  float* __restrict__ out) {
    __shared__ float sw[1056];                       // 1024 + 32 pad
    const int tid  = threadIdx.x;
    const int lane = tid & 31;
    const int wi   = tid >> 5;
    const int jb   = blockIdx.x * 1024;
    const int b0   = blockIdx.y * ROWS_PER_BLOCK;
    const int nB   = lane * 32 + wi * 4;             // mapping-B base

    // ---- prologue independent of kernel 1 (overlapped via PDL) ----
    float xs[ROWS_PER_BLOCK];
    #pragma unroll
    for (int q = 0; q < ROWS_PER_BLOCK; q++)
        xs[q] = __ldg(x + b0 + q);
    const float4 s2q = *(const float4*)(s2 + jb + nB);

#if __CUDA_ARCH__ >= 900
    cudaGridDependencySynchronize();                 // wait for d_z
#endif

    // ---- mapping A load (coalesced) + bits 0..6 ----
    float rr[4];
    #pragma unroll
    for (int k = 0; k < 4; k++)
        rr[k] = d_z[jb + wi * 128 + k * 32 + lane];

    #pragma unroll
    for (int m = 1; m <= 16; m <<= 1) {              // bits 0..4 (lane)
        const float sgn = (lane & m) ? -1.0f : 1.0f;
        #pragma unroll
        for (int k = 0; k < 4; k++) {
            float o = __shfl_xor_sync(0xffffffffu, rr[k], m);
            rr[k] = fmaf(sgn, rr[k], o);
        }
    }
    { // bit 5 (k bit 0)
        float a0 = rr[0], c0 = rr[1], a1 = rr[2], c1 = rr[3];
        rr[0] = a0 + c0; rr[1] = a0 - c0;
        rr[2] = a1 + c1; rr[3] = a1 - c1;
    }
    { // bit 6 (k bit 1)
        float a0 = rr[0], c0 = rr[2], a1 = rr[1], c1 = rr[3];
        rr[0] = a0 + c0; rr[2] = a0 - c0;
        rr[1] = a1 + c1; rr[3] = a1 - c1;
    }

    // ---- transpose A -> B (padded, conflict-free) ----
    #pragma unroll
    for (int k = 0; k < 4; k++) {
        int n = wi * 128 + k * 32 + lane;
        sw[n + (n >> 5)] = rr[k];
    }
    __syncthreads();

    float v[4];
    #pragma unroll
    for (int m = 0; m < 4; m++) {
        int n = nB + m;
        v[m] = sw[n + (n >> 5)];
    }

    // ---- bits 7..9 via lane bits 2..4 ----
    #pragma unroll
    for (int mm = 4; mm <= 16; mm <<= 1) {
        const float sgn = (lane & mm) ? -1.0f : 1.0f;
        #pragma unroll
        for (int m = 0; m < 4; m++) {
            float o = __shfl_xor_sync(0xffffffffu, v[m], mm);
            v[m] = fmaf(sgn, v[m], o);
        }
    }

    // ---- apply s2, transpose back so each thread owns 4 contiguous cols ----
    v[0] *= s2q.x; v[1] *= s2q.y; v[2] *= s2q.z; v[3] *= s2q.w;
    #pragma unroll
    for (int m = 0; m < 4; m++) {                    // same slots this thread read
        int n = nB + m;
        sw[n + (n >> 5)] = v[m];
    }
    __syncthreads();

    const int nf = tid * 4;
    float4 w4;
    w4.x = sw[nf + 0 + (nf >> 5)];
    w4.y = sw[nf + 1 + (nf >> 5)];
    w4.z = sw[nf + 2 + (nf >> 5)];
    w4.w = sw[nf + 3 + (nf >> 5)];
    const int jbase = jb + nf;

    // ---- stream the outer product (at the measured store roofline) ----
    #pragma unroll
    for (int q = 0; q < ROWS_PER_BLOCK; q++) {
        float xv = xs[q];
        float4 o = make_float4(xv * w4.x, xv * w4.y, xv * w4.z, xv * w4.w);
        __stcs((float4*)(out + (size_t)(b0 + q) * D + jbase), o);
    }
}

extern "C" void kernel_launch(void* const* d_in, const int* in_sizes, int n_in,
                              void* d_out, int out_size) {
    const float* x     = (const float*)d_in[0];  // (4096, 1)
    const float* s1    = (const float*)d_in[1];  // (8192,)
    const float* s2    = (const float*)d_in[2];  // (8192,)
    const float* g_mu  = (const float*)d_in[3];  // (8192,)
    const float* g_rho = (const float*)d_in[4];  // (8192,)
    const float* eps   = (const float*)d_in[5];  // (8192,)
    float* out = (float*)d_out;                  // (4096, 8192) f32

    stageA_kernel<<<16, 64>>>(s1, g_mu, g_rho, eps);

    cudaLaunchConfig_t cfg = {};
    cfg.gridDim  = dim3(D / 1024, BATCH / ROWS_PER_BLOCK, 1);  // (8, 256)
    cfg.blockDim = dim3(256, 1, 1);
    cfg.stream   = 0;
    cudaLaunchAttribute attr;
    attr.id = cudaLaunchAttributeProgrammaticStreamSerialization;
    attr.val.programmaticStreamSerializationAllowed = 1;
    cfg.attrs    = &attr;
    cfg.numAttrs = 1;
    cudaLaunchKernelEx(&cfg, outer_kernel, x, s2, out);
}